// round 1
// baseline (speedup 1.0000x reference)
#include <cuda_runtime.h>
#include <cuda_bf16.h>
#include <cstdint>
#include <cstddef>

// ---------------------------------------------------------------------------
// MinGRU (2 layers), B=8, S=8192, DIN=DH=256.
//   layer: gh = x @ W^T + b ; gate=gh[:,:256], hidden=gh[:,256:]
//   a = sigmoid(-gate), v = sigmoid(gate)*g(hidden), g(x)= x+0.5 (x>=0) else sigmoid(x)
//   h_t = a_t*h_{t-1} + v_t, h0 = 0.5   (linear-space equivalent of reference log scan)
// Output: out1 (8,8192,256) fp32 then h (2,8,1,256) fp32.
// ---------------------------------------------------------------------------

#define M_ROWS   65536
#define KDIM     256
#define NDIM     512
#define BATCH    8
#define SEQ      8192
#define NCH      64
#define CHLEN    128
#define OUT1_ELEMS 16777216

// -------------------- scratch (device globals; no allocation) --------------
__device__ __nv_bfloat16 g_xhi[16777216];     // 32 MB  (A operand hi; reused as out0 hi)
__device__ __nv_bfloat16 g_xlo[16777216];     // 32 MB  (A operand lo; reused as out0 lo)
__device__ float2        g_av [16777216];     // 128 MB (interleaved a,v; reused per layer)
__device__ __nv_bfloat16 g_whi[2][131072];    // W split hi, interleaved rows
__device__ __nv_bfloat16 g_wlo[2][131072];    // W split lo
__device__ float         g_bc [2][512];       // bias, interleaved
__device__ float2        g_agg[BATCH * NCH * 256];
__device__ float         g_h0 [BATCH * NCH * 256];

// -------------------- small helpers ----------------------------------------
__device__ __forceinline__ void cp16(void* dst, const void* src) {
    uint32_t d = (uint32_t)__cvta_generic_to_shared(dst);
    asm volatile("cp.async.cg.shared.global [%0], [%1], 16;\n" :: "r"(d), "l"(src));
}
#define CP_COMMIT() asm volatile("cp.async.commit_group;\n" ::: "memory")
#define CP_WAIT1()  asm volatile("cp.async.wait_group 1;\n" ::: "memory")

__device__ __forceinline__ void ldsm_x4(uint32_t (&r)[4], const void* p) {
    uint32_t a = (uint32_t)__cvta_generic_to_shared(p);
    asm volatile("ldmatrix.sync.aligned.m8n8.x4.shared.b16 {%0,%1,%2,%3}, [%4];"
                 : "=r"(r[0]), "=r"(r[1]), "=r"(r[2]), "=r"(r[3]) : "r"(a));
}

__device__ __forceinline__ void mma16816(float* c, const uint32_t* a, uint32_t b0, uint32_t b1) {
    asm volatile(
        "mma.sync.aligned.m16n8k16.row.col.f32.bf16.bf16.f32 "
        "{%0,%1,%2,%3}, {%4,%5,%6,%7}, {%8,%9}, {%0,%1,%2,%3};"
        : "+f"(c[0]), "+f"(c[1]), "+f"(c[2]), "+f"(c[3])
        : "r"(a[0]), "r"(a[1]), "r"(a[2]), "r"(a[3]), "r"(b0), "r"(b1));
}

// a = sigmoid(-gate), v = sigmoid(gate)*g(hidden)
__device__ __forceinline__ float2 av_from(float gate, float hid) {
    float e   = __expf(-fabsf(gate));
    float inv = 1.0f / (1.0f + e);
    float z, a;
    if (gate >= 0.0f) { z = inv;     a = e * inv; }
    else              { z = e * inv; a = inv;     }
    float g = (hid >= 0.0f) ? (hid + 0.5f) : (1.0f / (1.0f + __expf(-hid)));
    return make_float2(a, z * g);
}

// -------------------- conversion kernels -----------------------------------
__global__ void convert_x_kernel(const float* __restrict__ x) {
    size_t i = (size_t)blockIdx.x * blockDim.x + threadIdx.x;  // 4-elem groups
    float4 v = reinterpret_cast<const float4*>(x)[i];
    float vv[4] = {v.x, v.y, v.z, v.w};
    ushort4 hi, lo;
    unsigned short* hp = &hi.x;
    unsigned short* lp = &lo.x;
#pragma unroll
    for (int j = 0; j < 4; j++) {
        __nv_bfloat16 h = __float2bfloat16(vv[j]);
        float r = vv[j] - __bfloat162float(h);
        __nv_bfloat16 l = __float2bfloat16(r);
        hp[j] = __bfloat16_as_ushort(h);
        lp[j] = __bfloat16_as_ushort(l);
    }
    reinterpret_cast<ushort4*>(g_xhi)[i] = hi;
    reinterpret_cast<ushort4*>(g_xlo)[i] = lo;
}

// interleave W rows: dest row 2d = gate_d (src row d), 2d+1 = hidden_d (src row 256+d)
__global__ void convert_w_kernel(const float* __restrict__ W0, const float* __restrict__ W1) {
    int idx = blockIdx.x * blockDim.x + threadIdx.x;  // 0..262143
    int l = idx >> 17;
    int r = (idx >> 8) & 511;
    int k = idx & 255;
    const float* W = l ? W1 : W0;
    int src = (r & 1) ? (256 + (r >> 1)) : (r >> 1);
    float w = W[src * 256 + k];
    __nv_bfloat16 h = __float2bfloat16(w);
    g_whi[l][r * 256 + k] = h;
    g_wlo[l][r * 256 + k] = __float2bfloat16(w - __bfloat162float(h));
}

__global__ void convert_b_kernel(const float* __restrict__ b0, const float* __restrict__ b1) {
    int idx = blockIdx.x * blockDim.x + threadIdx.x;  // 0..1023
    int l = idx >> 9, n = idx & 511;
    int src = (n & 1) ? (256 + (n >> 1)) : (n >> 1);
    g_bc[l][n] = (l ? b1 : b0)[src];
}

// -------------------- GEMM + epilogue --------------------------------------
// C(M=65536, N=512) = A @ W^T with fp32 emulation via 3 bf16 passes:
//   seg0: Ahi*Whi   seg1: Ahi*Wlo   seg2: Alo*Whi
// Block tile 128x128, BK=32, 24 K-iterations total, 2-stage cp.async pipeline.
// Epilogue: col pair (2d, 2d+1) = (gate_d, hidden_d) -> write float2 av.
__global__ void __launch_bounds__(256) gemm_kernel(int layer) {
    const __nv_bfloat16* __restrict__ Ahi = g_xhi;
    const __nv_bfloat16* __restrict__ Alo = g_xlo;
    const __nv_bfloat16* __restrict__ Whi = g_whi[layer];
    const __nv_bfloat16* __restrict__ Wlo = g_wlo[layer];
    const float* __restrict__ bc = g_bc[layer];

    __shared__ __nv_bfloat16 As[2][128][40];
    __shared__ __nv_bfloat16 Bs[2][128][40];

    const int tid  = threadIdx.x;
    const int lane = tid & 31;
    const int warp = tid >> 5;
    const int wm   = warp & 3;   // 4 warps along M (32 rows each)
    const int wn   = warp >> 2;  // 2 warps along N (64 cols each)
    const int m0   = blockIdx.y * 128;
    const int n0   = blockIdx.x * 128;

    float acc[2][8][4];
#pragma unroll
    for (int i = 0; i < 2; i++)
#pragma unroll
        for (int j = 0; j < 8; j++)
#pragma unroll
            for (int q = 0; q < 4; q++) acc[i][j][q] = 0.0f;

    auto load_tile = [&](int buf, int it) {
        const __nv_bfloat16* gA = (it >= 16) ? Alo : Ahi;
        const __nv_bfloat16* gB = (it >= 8 && it < 16) ? Wlo : Whi;
        int kb = (it & 7) * 32;
#pragma unroll
        for (int i = 0; i < 2; i++) {
            int idx = tid * 2 + i;          // 0..511
            int row = idx >> 2;
            int c   = (idx & 3) * 8;
            cp16(&As[buf][row][c], gA + (size_t)(m0 + row) * KDIM + kb + c);
            cp16(&Bs[buf][row][c], gB + (size_t)(n0 + row) * KDIM + kb + c);
        }
    };

    load_tile(0, 0); CP_COMMIT();
    load_tile(1, 1); CP_COMMIT();

    for (int it = 0; it < 24; ++it) {
        int buf = it & 1;
        CP_WAIT1();
        __syncthreads();
#pragma unroll
        for (int ks = 0; ks < 2; ++ks) {
            int k0 = ks * 16;
            uint32_t af[2][4];
#pragma unroll
            for (int mi = 0; mi < 2; mi++) {
                int r  = wm * 32 + mi * 16 + (lane & 7) + ((lane & 8) ? 8 : 0);
                int cc = k0 + ((lane & 16) ? 8 : 0);
                ldsm_x4(af[mi], &As[buf][r][cc]);
            }
            uint32_t bq[4][4];
#pragma unroll
            for (int nj = 0; nj < 4; nj++) {
                int r  = wn * 64 + nj * 16 + ((lane & 16) ? 8 : 0) + (lane & 7);
                int cc = k0 + ((lane & 8) ? 8 : 0);
                ldsm_x4(bq[nj], &Bs[buf][r][cc]);
            }
#pragma unroll
            for (int mi = 0; mi < 2; mi++)
#pragma unroll
                for (int ni = 0; ni < 8; ni++)
                    mma16816(acc[mi][ni], af[mi], bq[ni >> 1][(ni & 1) * 2],
                             bq[ni >> 1][(ni & 1) * 2 + 1]);
        }
        __syncthreads();
        if (it + 2 < 24) load_tile(buf, it + 2);
        CP_COMMIT();
    }

    // epilogue: fragment cols 2*(lane%4)+{0,1} are (gate, hidden) of channel d
    const int tig = lane & 3;
    const int grp = lane >> 2;
#pragma unroll
    for (int mi = 0; mi < 2; mi++) {
        int r0 = m0 + wm * 32 + mi * 16 + grp;
#pragma unroll
        for (int ni = 0; ni < 8; ni++) {
            int col = n0 + wn * 64 + ni * 8 + tig * 2;
            int d   = col >> 1;
            float bg = bc[col];
            float bh = bc[col + 1];
            g_av[(size_t)r0 * 256 + d] =
                av_from(acc[mi][ni][0] + bg, acc[mi][ni][1] + bh);
            g_av[(size_t)(r0 + 8) * 256 + d] =
                av_from(acc[mi][ni][2] + bg, acc[mi][ni][3] + bh);
        }
    }
}

// -------------------- chunked scan -----------------------------------------
// pass1: per (b, chunk, d) compute (A = prod a, V = scan value with h0=0)
__global__ void scan_pass1() {
    int b = blockIdx.x, ch = blockIdx.y, d = threadIdx.x;
    size_t base = ((size_t)(b * SEQ + ch * CHLEN)) * 256 + d;
    float A = 1.0f, V = 0.0f;
#pragma unroll 8
    for (int s = 0; s < CHLEN; s++) {
        float2 t = g_av[base + (size_t)s * 256];
        V = fmaf(t.x, V, t.y);
        A *= t.x;
    }
    g_agg[(b * NCH + ch) * 256 + d] = make_float2(A, V);
}

// combine: sequential over NCH chunk aggregates -> per-chunk starting h0
__global__ void scan_combine() {
    int b = blockIdx.x, d = threadIdx.x;
    float h = 0.5f;
#pragma unroll
    for (int c = 0; c < NCH; c++) {
        int i = (b * NCH + c) * 256 + d;
        g_h0[i] = h;
        float2 t = g_agg[i];
        h = fmaf(t.x, h, t.y);
    }
}

// pass3 layer 0: write out0 directly as bf16 hi/lo split (GEMM1 operand);
// last timestep -> h[0] tail of d_out
__global__ void scan_pass3_l0(float* __restrict__ dout) {
    int b = blockIdx.x, ch = blockIdx.y, d = threadIdx.x;
    float h = g_h0[(b * NCH + ch) * 256 + d];
    size_t row0 = (size_t)b * SEQ + ch * CHLEN;
#pragma unroll 4
    for (int s = 0; s < CHLEN; s++) {
        size_t idx = (row0 + s) * 256 + d;
        float2 t = g_av[idx];
        h = fmaf(t.x, h, t.y);
        __nv_bfloat16 hi = __float2bfloat16(h);
        g_xhi[idx] = hi;
        g_xlo[idx] = __float2bfloat16(h - __bfloat162float(hi));
    }
    if (ch == NCH - 1) dout[OUT1_ELEMS + b * 256 + d] = h;
}

// pass3 layer 1: write out1 fp32; last timestep -> h[1] tail
__global__ void scan_pass3_l1(float* __restrict__ dout) {
    int b = blockIdx.x, ch = blockIdx.y, d = threadIdx.x;
    float h = g_h0[(b * NCH + ch) * 256 + d];
    size_t row0 = (size_t)b * SEQ + ch * CHLEN;
#pragma unroll 4
    for (int s = 0; s < CHLEN; s++) {
        size_t idx = (row0 + s) * 256 + d;
        float2 t = g_av[idx];
        h = fmaf(t.x, h, t.y);
        dout[idx] = h;
    }
    if (ch == NCH - 1) dout[OUT1_ELEMS + 2048 + b * 256 + d] = h;
}

// -------------------- launch -----------------------------------------------
extern "C" void kernel_launch(void* const* d_in, const int* in_sizes, int n_in,
                              void* d_out, int out_size) {
    const float* x  = (const float*)d_in[0];
    const float* W0 = (const float*)d_in[1];
    const float* b0 = (const float*)d_in[2];
    const float* W1 = (const float*)d_in[3];
    const float* b1 = (const float*)d_in[4];
    float* out = (float*)d_out;

    convert_x_kernel<<<16384, 256>>>(x);
    convert_w_kernel<<<1024, 256>>>(W0, W1);
    convert_b_kernel<<<4, 256>>>(b0, b1);

    dim3 ggrid(4, 512);        // x = N blocks (fast) so A-panel reuse hits L2
    dim3 sgrid(BATCH, NCH);

    gemm_kernel<<<ggrid, 256>>>(0);
    scan_pass1<<<sgrid, 256>>>();
    scan_combine<<<BATCH, 256>>>();
    scan_pass3_l0<<<sgrid, 256>>>(out);

    gemm_kernel<<<ggrid, 256>>>(1);
    scan_pass1<<<sgrid, 256>>>();
    scan_combine<<<BATCH, 256>>>();
    scan_pass3_l1<<<sgrid, 256>>>(out);
}

// round 3
// speedup vs baseline: 1.0555x; 1.0555x over previous
#include <cuda_runtime.h>
#include <cuda_bf16.h>
#include <cstdint>
#include <cstddef>

// ---------------------------------------------------------------------------
// MinGRU (2 layers), B=8, S=8192, DIN=DH=256.
//   gh = x @ W^T + b; gate=gh[:,:256], hidden=gh[:,256:]
//   a = sigmoid(-gate), v = sigmoid(gate)*g(hidden), g(x)= x+0.5 (x>=0) else sigmoid(x)
//   h_t = a_t*h_{t-1} + v_t, h0 = 0.5  (linear-space equivalent of reference)
// fp32 GEMM emulated with 3 bf16 mma.sync passes: Ahi*Whi + Ahi*Wlo + Alo*Whi.
// R3: 4-stage cp.async pipeline + single barrier per K-iteration.
// ---------------------------------------------------------------------------

#define M_ROWS   65536
#define KDIM     256
#define NDIM     512
#define BATCH    8
#define SEQ      8192
#define NCH      64
#define CHLEN    128
#define OUT1_ELEMS 16777216

#define STAGES   4
#define A_PITCH  40                      // bf16 elements per SMEM row
#define A_STAGE_BYTES (128 * A_PITCH * 2)   // 10240
#define SMEM_BYTES (2 * STAGES * A_STAGE_BYTES)  // 81920 (As then Bs)

// -------------------- scratch (device globals; no allocation) --------------
__device__ __nv_bfloat16 g_xhi[16777216];     // 32 MB  (A hi; reused as out0 hi)
__device__ __nv_bfloat16 g_xlo[16777216];     // 32 MB  (A lo; reused as out0 lo)
__device__ float2        g_av [16777216];     // 128 MB (interleaved a,v per layer)
__device__ __nv_bfloat16 g_whi[2][131072];    // W hi, interleaved rows
__device__ __nv_bfloat16 g_wlo[2][131072];    // W lo
__device__ float         g_bc [2][512];       // bias, interleaved
__device__ float2        g_agg[BATCH * NCH * 256];
__device__ float         g_h0 [BATCH * NCH * 256];

// -------------------- small helpers ----------------------------------------
__device__ __forceinline__ void cp16(void* dst, const void* src) {
    uint32_t d = (uint32_t)__cvta_generic_to_shared(dst);
    asm volatile("cp.async.cg.shared.global [%0], [%1], 16;\n" :: "r"(d), "l"(src));
}
#define CP_COMMIT() asm volatile("cp.async.commit_group;\n" ::: "memory")
#define CP_WAIT2()  asm volatile("cp.async.wait_group 2;\n" ::: "memory")

__device__ __forceinline__ void ldsm_x4(uint32_t (&r)[4], const void* p) {
    uint32_t a = (uint32_t)__cvta_generic_to_shared(p);
    asm volatile("ldmatrix.sync.aligned.m8n8.x4.shared.b16 {%0,%1,%2,%3}, [%4];"
                 : "=r"(r[0]), "=r"(r[1]), "=r"(r[2]), "=r"(r[3]) : "r"(a));
}

__device__ __forceinline__ void mma16816(float* c, const uint32_t* a, uint32_t b0, uint32_t b1) {
    asm volatile(
        "mma.sync.aligned.m16n8k16.row.col.f32.bf16.bf16.f32 "
        "{%0,%1,%2,%3}, {%4,%5,%6,%7}, {%8,%9}, {%0,%1,%2,%3};"
        : "+f"(c[0]), "+f"(c[1]), "+f"(c[2]), "+f"(c[3])
        : "r"(a[0]), "r"(a[1]), "r"(a[2]), "r"(a[3]), "r"(b0), "r"(b1));
}

// a = sigmoid(-gate), v = sigmoid(gate)*g(hidden)
__device__ __forceinline__ float2 av_from(float gate, float hid) {
    float e   = __expf(-fabsf(gate));
    float inv = 1.0f / (1.0f + e);
    float z, a;
    if (gate >= 0.0f) { z = inv;     a = e * inv; }
    else              { z = e * inv; a = inv;     }
    float g = (hid >= 0.0f) ? (hid + 0.5f) : (1.0f / (1.0f + __expf(-hid)));
    return make_float2(a, z * g);
}

// -------------------- conversion kernels -----------------------------------
__global__ void convert_x_kernel(const float* __restrict__ x) {
    size_t i = (size_t)blockIdx.x * blockDim.x + threadIdx.x;  // 4-elem groups
    float4 v = reinterpret_cast<const float4*>(x)[i];
    float vv[4] = {v.x, v.y, v.z, v.w};
    ushort4 hi, lo;
    unsigned short* hp = &hi.x;
    unsigned short* lp = &lo.x;
#pragma unroll
    for (int j = 0; j < 4; j++) {
        __nv_bfloat16 h = __float2bfloat16(vv[j]);
        float r = vv[j] - __bfloat162float(h);
        __nv_bfloat16 l = __float2bfloat16(r);
        hp[j] = __bfloat16_as_ushort(h);
        lp[j] = __bfloat16_as_ushort(l);
    }
    reinterpret_cast<ushort4*>(g_xhi)[i] = hi;
    reinterpret_cast<ushort4*>(g_xlo)[i] = lo;
}

// interleave W rows: dest row 2d = gate_d (src row d), 2d+1 = hidden_d (src row 256+d)
__global__ void convert_w_kernel(const float* __restrict__ W0, const float* __restrict__ W1) {
    int idx = blockIdx.x * blockDim.x + threadIdx.x;  // 0..262143
    int l = idx >> 17;
    int r = (idx >> 8) & 511;
    int k = idx & 255;
    const float* W = l ? W1 : W0;
    int src = (r & 1) ? (256 + (r >> 1)) : (r >> 1);
    float w = W[src * 256 + k];
    __nv_bfloat16 h = __float2bfloat16(w);
    g_whi[l][r * 256 + k] = h;
    g_wlo[l][r * 256 + k] = __float2bfloat16(w - __bfloat162float(h));
}

__global__ void convert_b_kernel(const float* __restrict__ b0, const float* __restrict__ b1) {
    int idx = blockIdx.x * blockDim.x + threadIdx.x;  // 0..1023
    int l = idx >> 9, n = idx & 511;
    int src = (n & 1) ? (256 + (n >> 1)) : (n >> 1);
    g_bc[l][n] = (l ? b1 : b0)[src];
}

// -------------------- GEMM + epilogue --------------------------------------
// C(M=65536, N=512) = A @ W^T with fp32 emulation via 3 bf16 passes:
//   it 0..7:  Ahi*Whi   it 8..15: Ahi*Wlo   it 16..23: Alo*Whi   (BK=32)
// Block tile 128x128, 4-stage cp.async pipeline, one barrier per iteration.
// Epilogue: col pair (2d, 2d+1) = (gate_d, hidden_d) -> write float2 av.
__global__ void __launch_bounds__(256, 2) gemm_kernel(int layer) {
    const __nv_bfloat16* __restrict__ Ahi = g_xhi;
    const __nv_bfloat16* __restrict__ Alo = g_xlo;
    const __nv_bfloat16* __restrict__ Whi = g_whi[layer];
    const __nv_bfloat16* __restrict__ Wlo = g_wlo[layer];
    const float* __restrict__ bc = g_bc[layer];

    extern __shared__ __align__(128) __nv_bfloat16 smem[];
    // As[stage][128][A_PITCH], Bs[stage][128][A_PITCH]
    __nv_bfloat16* As = smem;
    __nv_bfloat16* Bs = smem + STAGES * 128 * A_PITCH;

    const int tid  = threadIdx.x;
    const int lane = tid & 31;
    const int warp = tid >> 5;
    const int wm   = warp & 3;   // 4 warps along M (32 rows each)
    const int wn   = warp >> 2;  // 2 warps along N (64 cols each)
    const int m0   = blockIdx.y * 128;
    const int n0   = blockIdx.x * 128;

    float acc[2][8][4];
#pragma unroll
    for (int i = 0; i < 2; i++)
#pragma unroll
        for (int j = 0; j < 8; j++)
#pragma unroll
            for (int q = 0; q < 4; q++) acc[i][j][q] = 0.0f;

    auto load_tile = [&](int it) {
        int buf = it & (STAGES - 1);
        const __nv_bfloat16* gA = (it >= 16) ? Alo : Ahi;
        const __nv_bfloat16* gB = (it >= 8 && it < 16) ? Wlo : Whi;
        int kb = (it & 7) * 32;
        __nv_bfloat16* as = As + buf * 128 * A_PITCH;
        __nv_bfloat16* bs = Bs + buf * 128 * A_PITCH;
#pragma unroll
        for (int i = 0; i < 2; i++) {
            int idx = tid * 2 + i;          // 0..511
            int row = idx >> 2;
            int c   = (idx & 3) * 8;
            cp16(as + row * A_PITCH + c, gA + (size_t)(m0 + row) * KDIM + kb + c);
            cp16(bs + row * A_PITCH + c, gB + (size_t)(n0 + row) * KDIM + kb + c);
        }
    };

    load_tile(0); CP_COMMIT();
    load_tile(1); CP_COMMIT();
    load_tile(2); CP_COMMIT();

    for (int it = 0; it < 24; ++it) {
        int buf = it & (STAGES - 1);
        const __nv_bfloat16* as = As + buf * 128 * A_PITCH;
        const __nv_bfloat16* bs = Bs + buf * 128 * A_PITCH;
        CP_WAIT2();             // stage `it` complete (<=2 younger groups pending)
        __syncthreads();        // all warps done reading buf (it-1)%4 == (it+3)%4
#pragma unroll
        for (int ks = 0; ks < 2; ++ks) {
            int k0 = ks * 16;
            uint32_t af[2][4];
#pragma unroll
            for (int mi = 0; mi < 2; mi++) {
                int r  = wm * 32 + mi * 16 + (lane & 7) + ((lane & 8) ? 8 : 0);
                int cc = k0 + ((lane & 16) ? 8 : 0);
                ldsm_x4(af[mi], as + r * A_PITCH + cc);
            }
            uint32_t bq[4][4];
#pragma unroll
            for (int nj = 0; nj < 4; nj++) {
                int r  = wn * 64 + nj * 16 + ((lane & 16) ? 8 : 0) + (lane & 7);
                int cc = k0 + ((lane & 8) ? 8 : 0);
                ldsm_x4(bq[nj], bs + r * A_PITCH + cc);
            }
#pragma unroll
            for (int mi = 0; mi < 2; mi++)
#pragma unroll
                for (int ni = 0; ni < 8; ni++)
                    mma16816(acc[mi][ni], af[mi], bq[ni >> 1][(ni & 1) * 2],
                             bq[ni >> 1][(ni & 1) * 2 + 1]);
        }
        if (it + 3 < 24) load_tile(it + 3);
        CP_COMMIT();            // commit (possibly empty) to keep group count uniform
    }

    // epilogue: fragment cols 2*(lane%4)+{0,1} are (gate, hidden) of channel d
    const int tig = lane & 3;
    const int grp = lane >> 2;
#pragma unroll
    for (int mi = 0; mi < 2; mi++) {
        int r0 = m0 + wm * 32 + mi * 16 + grp;
#pragma unroll
        for (int ni = 0; ni < 8; ni++) {
            int col = n0 + wn * 64 + ni * 8 + tig * 2;
            int d   = col >> 1;
            float bg = bc[col];
            float bh = bc[col + 1];
            g_av[(size_t)r0 * 256 + d] =
                av_from(acc[mi][ni][0] + bg, acc[mi][ni][1] + bh);
            g_av[(size_t)(r0 + 8) * 256 + d] =
                av_from(acc[mi][ni][2] + bg, acc[mi][ni][3] + bh);
        }
    }
}

// -------------------- chunked scan -----------------------------------------
// pass1: per (b, chunk, d) compute (A = prod a, V = scan value with h0=0)
__global__ void scan_pass1() {
    int b = blockIdx.x, ch = blockIdx.y, d = threadIdx.x;
    size_t base = ((size_t)(b * SEQ + ch * CHLEN)) * 256 + d;
    float A = 1.0f, V = 0.0f;
#pragma unroll 8
    for (int s = 0; s < CHLEN; s++) {
        float2 t = g_av[base + (size_t)s * 256];
        V = fmaf(t.x, V, t.y);
        A *= t.x;
    }
    g_agg[(b * NCH + ch) * 256 + d] = make_float2(A, V);
}

// combine: sequential over NCH chunk aggregates -> per-chunk starting h0
__global__ void scan_combine() {
    int b = blockIdx.x, d = threadIdx.x;
    float h = 0.5f;
#pragma unroll
    for (int c = 0; c < NCH; c++) {
        int i = (b * NCH + c) * 256 + d;
        g_h0[i] = h;
        float2 t = g_agg[i];
        h = fmaf(t.x, h, t.y);
    }
}

// pass3 layer 0: write out0 directly as bf16 hi/lo split (GEMM1 operand);
// last timestep -> h[0] tail of d_out
__global__ void scan_pass3_l0(float* __restrict__ dout) {
    int b = blockIdx.x, ch = blockIdx.y, d = threadIdx.x;
    float h = g_h0[(b * NCH + ch) * 256 + d];
    size_t row0 = (size_t)b * SEQ + ch * CHLEN;
#pragma unroll 4
    for (int s = 0; s < CHLEN; s++) {
        size_t idx = (row0 + s) * 256 + d;
        float2 t = g_av[idx];
        h = fmaf(t.x, h, t.y);
        __nv_bfloat16 hi = __float2bfloat16(h);
        g_xhi[idx] = hi;
        g_xlo[idx] = __float2bfloat16(h - __bfloat162float(hi));
    }
    if (ch == NCH - 1) dout[OUT1_ELEMS + b * 256 + d] = h;
}

// pass3 layer 1: write out1 fp32; last timestep -> h[1] tail
__global__ void scan_pass3_l1(float* __restrict__ dout) {
    int b = blockIdx.x, ch = blockIdx.y, d = threadIdx.x;
    float h = g_h0[(b * NCH + ch) * 256 + d];
    size_t row0 = (size_t)b * SEQ + ch * CHLEN;
#pragma unroll 4
    for (int s = 0; s < CHLEN; s++) {
        size_t idx = (row0 + s) * 256 + d;
        float2 t = g_av[idx];
        h = fmaf(t.x, h, t.y);
        dout[idx] = h;
    }
    if (ch == NCH - 1) dout[OUT1_ELEMS + 2048 + b * 256 + d] = h;
}

// -------------------- launch -----------------------------------------------
extern "C" void kernel_launch(void* const* d_in, const int* in_sizes, int n_in,
                              void* d_out, int out_size) {
    const float* x  = (const float*)d_in[0];
    const float* W0 = (const float*)d_in[1];
    const float* b0 = (const float*)d_in[2];
    const float* W1 = (const float*)d_in[3];
    const float* b1 = (const float*)d_in[4];
    float* out = (float*)d_out;

    cudaFuncSetAttribute(gemm_kernel,
                         cudaFuncAttributeMaxDynamicSharedMemorySize, SMEM_BYTES);

    convert_x_kernel<<<16384, 256>>>(x);
    convert_w_kernel<<<1024, 256>>>(W0, W1);
    convert_b_kernel<<<4, 256>>>(b0, b1);

    dim3 ggrid(4, 512);        // x = N blocks (fast) so A-panel reuse hits L2
    dim3 sgrid(BATCH, NCH);

    gemm_kernel<<<ggrid, 256, SMEM_BYTES>>>(0);
    scan_pass1<<<sgrid, 256>>>();
    scan_combine<<<BATCH, 256>>>();
    scan_pass3_l0<<<sgrid, 256>>>(out);

    gemm_kernel<<<ggrid, 256, SMEM_BYTES>>>(1);
    scan_pass1<<<sgrid, 256>>>();
    scan_combine<<<BATCH, 256>>>();
    scan_pass3_l1<<<sgrid, 256>>>(out);
}

// round 5
// speedup vs baseline: 1.1342x; 1.0746x over previous
#include <cuda_runtime.h>
#include <cuda_bf16.h>
#include <cstdint>
#include <cstddef>

// ---------------------------------------------------------------------------
// MinGRU (2 layers), B=8, S=8192, DIN=DH=256.
//   gh = x @ W^T + b; a = sigmoid(-gate); v = sigmoid(gate)*g(hidden)
//   h_t = a_t*h_{t-1} + v_t, h0 = 0.5  (linear-space equivalent of reference)
// fp32 GEMM emulated with 3 bf16 mma.sync passes: Ahi*Whi + Ahi*Wlo + Alo*Whi.
// R4: BK=64 x 3-stage pipeline (12 barriers), loads issued right after barrier,
//     scan pass1 fused into the GEMM epilogue via SMEM staging.
// ---------------------------------------------------------------------------

#define M_ROWS   65536
#define KDIM     256
#define NDIM     512
#define BATCH    8
#define SEQ      8192
#define NCH      64
#define CHLEN    128
#define OUT1_ELEMS 16777216

#define STAGES   3
#define BK       64
#define A_PITCH  72                          // bf16 elements per SMEM row
#define STAGE_ELEMS (128 * A_PITCH)          // per operand per stage
#define SMEM_BYTES (STAGES * 2 * STAGE_ELEMS * 2)   // 110592

// -------------------- scratch (device globals; no allocation) --------------
__device__ __nv_bfloat16 g_xhi[16777216];     // 32 MB  (A hi; reused as out0 hi)
__device__ __nv_bfloat16 g_xlo[16777216];     // 32 MB  (A lo; reused as out0 lo)
__device__ float2        g_av [16777216];     // 128 MB (interleaved a,v per layer)
__device__ __nv_bfloat16 g_whi[2][131072];    // W hi, interleaved rows
__device__ __nv_bfloat16 g_wlo[2][131072];    // W lo
__device__ float         g_bc [2][512];       // bias, interleaved
__device__ float2        g_agg[BATCH * NCH * 256];
__device__ float         g_h0 [BATCH * NCH * 256];

// -------------------- small helpers ----------------------------------------
__device__ __forceinline__ void cp16(void* dst, const void* src) {
    uint32_t d = (uint32_t)__cvta_generic_to_shared(dst);
    asm volatile("cp.async.cg.shared.global [%0], [%1], 16;\n" :: "r"(d), "l"(src));
}
#define CP_COMMIT() asm volatile("cp.async.commit_group;\n" ::: "memory")
#define CP_WAIT1()  asm volatile("cp.async.wait_group 1;\n" ::: "memory")

__device__ __forceinline__ void ldsm_x4(uint32_t (&r)[4], const void* p) {
    uint32_t a = (uint32_t)__cvta_generic_to_shared(p);
    asm volatile("ldmatrix.sync.aligned.m8n8.x4.shared.b16 {%0,%1,%2,%3}, [%4];"
                 : "=r"(r[0]), "=r"(r[1]), "=r"(r[2]), "=r"(r[3]) : "r"(a));
}

__device__ __forceinline__ void mma16816(float* c, const uint32_t* a, uint32_t b0, uint32_t b1) {
    asm volatile(
        "mma.sync.aligned.m16n8k16.row.col.f32.bf16.bf16.f32 "
        "{%0,%1,%2,%3}, {%4,%5,%6,%7}, {%8,%9}, {%0,%1,%2,%3};"
        : "+f"(c[0]), "+f"(c[1]), "+f"(c[2]), "+f"(c[3])
        : "r"(a[0]), "r"(a[1]), "r"(a[2]), "r"(a[3]), "r"(b0), "r"(b1));
}

// a = sigmoid(-gate), v = sigmoid(gate)*g(hidden)
__device__ __forceinline__ float2 av_from(float gate, float hid) {
    float e   = __expf(-fabsf(gate));
    float inv = 1.0f / (1.0f + e);
    float z, a;
    if (gate >= 0.0f) { z = inv;     a = e * inv; }
    else              { z = e * inv; a = inv;     }
    float g = (hid >= 0.0f) ? (hid + 0.5f) : (1.0f / (1.0f + __expf(-hid)));
    return make_float2(a, z * g);
}

// -------------------- conversion kernels -----------------------------------
__global__ void convert_x_kernel(const float* __restrict__ x) {
    size_t i = (size_t)blockIdx.x * blockDim.x + threadIdx.x;  // 4-elem groups
    float4 v = reinterpret_cast<const float4*>(x)[i];
    float vv[4] = {v.x, v.y, v.z, v.w};
    ushort4 hi, lo;
    unsigned short* hp = &hi.x;
    unsigned short* lp = &lo.x;
#pragma unroll
    for (int j = 0; j < 4; j++) {
        __nv_bfloat16 h = __float2bfloat16(vv[j]);
        float r = vv[j] - __bfloat162float(h);
        __nv_bfloat16 l = __float2bfloat16(r);
        hp[j] = __bfloat16_as_ushort(h);
        lp[j] = __bfloat16_as_ushort(l);
    }
    reinterpret_cast<ushort4*>(g_xhi)[i] = hi;
    reinterpret_cast<ushort4*>(g_xlo)[i] = lo;
}

// interleave W rows: dest row 2d = gate_d (src row d), 2d+1 = hidden_d (src row 256+d)
__global__ void convert_w_kernel(const float* __restrict__ W0, const float* __restrict__ W1) {
    int idx = blockIdx.x * blockDim.x + threadIdx.x;  // 0..262143
    int l = idx >> 17;
    int r = (idx >> 8) & 511;
    int k = idx & 255;
    const float* W = l ? W1 : W0;
    int src = (r & 1) ? (256 + (r >> 1)) : (r >> 1);
    float w = W[src * 256 + k];
    __nv_bfloat16 h = __float2bfloat16(w);
    g_whi[l][r * 256 + k] = h;
    g_wlo[l][r * 256 + k] = __float2bfloat16(w - __bfloat162float(h));
}

__global__ void convert_b_kernel(const float* __restrict__ b0, const float* __restrict__ b1) {
    int idx = blockIdx.x * blockDim.x + threadIdx.x;  // 0..1023
    int l = idx >> 9, n = idx & 511;
    int src = (n & 1) ? (256 + (n >> 1)) : (n >> 1);
    g_bc[l][n] = (l ? b1 : b0)[src];
}

// -------------------- GEMM + epilogue + fused pass1 -------------------------
// C(M=65536, N=512) = A @ W^T, fp32 emulation via 3 bf16 passes over BK=64 stages:
//   it 0..3: Ahi*Whi   it 4..7: Ahi*Wlo   it 8..11: Alo*Whi
// Block tile 128x128 (one scan chunk x 64 channels), 3-stage cp.async pipeline.
// Epilogue: (gate,hidden) col pairs -> (a,v); write g_av; stage in SMEM; 64
// threads reduce the 128-step chunk -> g_agg (this IS scan pass1).
__global__ void __launch_bounds__(256, 2) gemm_kernel(int layer) {
    const __nv_bfloat16* __restrict__ Ahi = g_xhi;
    const __nv_bfloat16* __restrict__ Alo = g_xlo;
    const __nv_bfloat16* __restrict__ Whi = g_whi[layer];
    const __nv_bfloat16* __restrict__ Wlo = g_wlo[layer];
    const float* __restrict__ bc = g_bc[layer];

    extern __shared__ __align__(128) __nv_bfloat16 smem[];
    __nv_bfloat16* As = smem;                              // [STAGES][128][A_PITCH]
    __nv_bfloat16* Bs = smem + STAGES * STAGE_ELEMS;       // [STAGES][128][A_PITCH]

    const int tid  = threadIdx.x;
    const int lane = tid & 31;
    const int warp = tid >> 5;
    const int wm   = warp & 3;   // 4 warps along M (32 rows each)
    const int wn   = warp >> 2;  // 2 warps along N (64 cols each)
    const int m0   = blockIdx.y * 128;
    const int n0   = blockIdx.x * 128;

    float acc[2][8][4];
#pragma unroll
    for (int i = 0; i < 2; i++)
#pragma unroll
        for (int j = 0; j < 8; j++)
#pragma unroll
            for (int q = 0; q < 4; q++) acc[i][j][q] = 0.0f;

    auto load_tile = [&](int it) {
        int buf = it % STAGES;
        const __nv_bfloat16* gA = (it >= 8) ? Alo : Ahi;
        const __nv_bfloat16* gB = (it >= 4 && it < 8) ? Wlo : Whi;
        int kb = (it & 3) * BK;
        __nv_bfloat16* as = As + buf * STAGE_ELEMS;
        __nv_bfloat16* bs = Bs + buf * STAGE_ELEMS;
#pragma unroll
        for (int i = 0; i < 4; i++) {
            int idx = tid + i * 256;        // 0..1023
            int row = idx >> 3;
            int c   = (idx & 7) * 8;
            cp16(as + row * A_PITCH + c, gA + (size_t)(m0 + row) * KDIM + kb + c);
            cp16(bs + row * A_PITCH + c, gB + (size_t)(n0 + row) * KDIM + kb + c);
        }
    };

    load_tile(0); CP_COMMIT();
    load_tile(1); CP_COMMIT();

    for (int it = 0; it < 12; ++it) {
        int buf = it % STAGES;
        const __nv_bfloat16* as = As + buf * STAGE_ELEMS;
        const __nv_bfloat16* bs = Bs + buf * STAGE_ELEMS;
        CP_WAIT1();             // stage `it` landed
        __syncthreads();        // all warps done with buf (it-1)%3 == (it+2)%3
        if (it + 2 < 12) load_tile(it + 2);   // issue loads BEFORE compute
        CP_COMMIT();
#pragma unroll
        for (int ks = 0; ks < 4; ++ks) {
            int k0 = ks * 16;
            uint32_t af[2][4];
#pragma unroll
            for (int mi = 0; mi < 2; mi++) {
                int r  = wm * 32 + mi * 16 + (lane & 15);
                int cc = k0 + ((lane & 16) ? 8 : 0);
                ldsm_x4(af[mi], as + r * A_PITCH + cc);
            }
            uint32_t bq[4][4];
#pragma unroll
            for (int nj = 0; nj < 4; nj++) {
                int r  = wn * 64 + nj * 16 + ((lane & 16) ? 8 : 0) + (lane & 7);
                int cc = k0 + ((lane & 8) ? 8 : 0);
                ldsm_x4(bq[nj], bs + r * A_PITCH + cc);
            }
#pragma unroll
            for (int mi = 0; mi < 2; mi++)
#pragma unroll
                for (int ni = 0; ni < 8; ni++)
                    mma16816(acc[mi][ni], af[mi], bq[ni >> 1][(ni & 1) * 2],
                             bq[ni >> 1][(ni & 1) * 2 + 1]);
        }
    }

    // ---------------- epilogue + fused scan pass1 ----------------
    __syncthreads();            // mainloop fully done; smem now reusable
    float2* av_sm = reinterpret_cast<float2*>(smem);   // [128][64] = 64KB

    const int tig = lane & 3;
    const int grp = lane >> 2;
#pragma unroll
    for (int mi = 0; mi < 2; mi++) {
        int s0 = wm * 32 + mi * 16 + grp;              // local row 0..127
#pragma unroll
        for (int ni = 0; ni < 8; ni++) {
            int col = n0 + wn * 64 + ni * 8 + tig * 2; // global interleaved col
            int chl = wn * 32 + ni * 4 + tig;          // local channel 0..63
            int d   = col >> 1;
            float bg = bc[col];
            float bh = bc[col + 1];
            float2 p0 = av_from(acc[mi][ni][0] + bg, acc[mi][ni][1] + bh);
            float2 p1 = av_from(acc[mi][ni][2] + bg, acc[mi][ni][3] + bh);
            g_av[(size_t)(m0 + s0) * 256 + d]     = p0;
            g_av[(size_t)(m0 + s0 + 8) * 256 + d] = p1;
            av_sm[s0 * 64 + chl]       = p0;
            av_sm[(s0 + 8) * 64 + chl] = p1;
        }
    }
    __syncthreads();
    if (tid < 64) {                                    // chunk reduction (pass1)
        const int b  = m0 >> 13;
        const int ck = (m0 >> 7) & 63;
        float A = 1.0f, V = 0.0f;
#pragma unroll 8
        for (int s = 0; s < CHLEN; s++) {
            float2 t = av_sm[s * 64 + tid];
            V = fmaf(t.x, V, t.y);
            A *= t.x;
        }
        g_agg[(b * NCH + ck) * 256 + (n0 >> 1) + tid] = make_float2(A, V);
    }
}

// -------------------- chunked scan -----------------------------------------
// combine: sequential over NCH chunk aggregates -> per-chunk starting h0
__global__ void scan_combine() {
    int b = blockIdx.x, d = threadIdx.x;
    float h = 0.5f;
#pragma unroll
    for (int c = 0; c < NCH; c++) {
        int i = (b * NCH + c) * 256 + d;
        g_h0[i] = h;
        float2 t = g_agg[i];
        h = fmaf(t.x, h, t.y);
    }
}

// pass3 layer 0: write out0 directly as bf16 hi/lo split (GEMM1 operand);
// last timestep -> h[0] tail of d_out
__global__ void scan_pass3_l0(float* __restrict__ dout) {
    int b = blockIdx.x, ch = blockIdx.y, d = threadIdx.x;
    float h = g_h0[(b * NCH + ch) * 256 + d];
    size_t row0 = (size_t)b * SEQ + ch * CHLEN;
#pragma unroll 4
    for (int s = 0; s < CHLEN; s++) {
        size_t idx = (row0 + s) * 256 + d;
        float2 t = g_av[idx];
        h = fmaf(t.x, h, t.y);
        __nv_bfloat16 hi = __float2bfloat16(h);
        g_xhi[idx] = hi;
        g_xlo[idx] = __float2bfloat16(h - __bfloat162float(hi));
    }
    if (ch == NCH - 1) dout[OUT1_ELEMS + b * 256 + d] = h;
}

// pass3 layer 1: write out1 fp32; last timestep -> h[1] tail
__global__ void scan_pass3_l1(float* __restrict__ dout) {
    int b = blockIdx.x, ch = blockIdx.y, d = threadIdx.x;
    float h = g_h0[(b * NCH + ch) * 256 + d];
    size_t row0 = (size_t)b * SEQ + ch * CHLEN;
#pragma unroll 4
    for (int s = 0; s < CHLEN; s++) {
        size_t idx = (row0 + s) * 256 + d;
        float2 t = g_av[idx];
        h = fmaf(t.x, h, t.y);
        dout[idx] = h;
    }
    if (ch == NCH - 1) dout[OUT1_ELEMS + 2048 + b * 256 + d] = h;
}

// -------------------- launch -----------------------------------------------
extern "C" void kernel_launch(void* const* d_in, const int* in_sizes, int n_in,
                              void* d_out, int out_size) {
    const float* x  = (const float*)d_in[0];
    const float* W0 = (const float*)d_in[1];
    const float* b0 = (const float*)d_in[2];
    const float* W1 = (const float*)d_in[3];
    const float* b1 = (const float*)d_in[4];
    float* out = (float*)d_out;

    cudaFuncSetAttribute(gemm_kernel,
                         cudaFuncAttributeMaxDynamicSharedMemorySize, SMEM_BYTES);

    convert_x_kernel<<<16384, 256>>>(x);
    convert_w_kernel<<<1024, 256>>>(W0, W1);
    convert_b_kernel<<<4, 256>>>(b0, b1);

    dim3 ggrid(4, 512);        // x = N blocks (fast) so A-panel reuse hits L2
    dim3 sgrid(BATCH, NCH);

    gemm_kernel<<<ggrid, 256, SMEM_BYTES>>>(0);   // includes fused pass1
    scan_combine<<<BATCH, 256>>>();
    scan_pass3_l0<<<sgrid, 256>>>(out);

    gemm_kernel<<<ggrid, 256, SMEM_BYTES>>>(1);   // includes fused pass1
    scan_combine<<<BATCH, 256>>>();
    scan_pass3_l1<<<sgrid, 256>>>(out);
}